// round 2
// baseline (speedup 1.0000x reference)
#include <cuda_runtime.h>
#include <cuda_bf16.h>
#include <stdint.h>

// loss = 2 - 2 * (sum_i feature[i, label[i]] / SCALE) / n
// feature: [n, C] float32, label: [n] int32 (JAX x64 disabled!), out: scalar f32.
// Only n gathered floats of feature are touched.

#define BLOCK 128
#define MAX_BLOCKS 1024

__device__ float g_partial[MAX_BLOCKS];

__global__ void center_gather_kernel(const float* __restrict__ feature,
                                     const int* __restrict__ label,
                                     int n, int C) {
    int tid = blockIdx.x * BLOCK + threadIdx.x;
    float v = 0.0f;
    if (tid < n) {
        int l = label[tid];
        v = feature[(size_t)tid * (size_t)C + (size_t)l];
    }
    // warp reduce
    #pragma unroll
    for (int off = 16; off > 0; off >>= 1)
        v += __shfl_xor_sync(0xFFFFFFFFu, v, off);

    __shared__ float warp_sums[BLOCK / 32];
    int wid = threadIdx.x >> 5;
    int lid = threadIdx.x & 31;
    if (lid == 0) warp_sums[wid] = v;
    __syncthreads();

    if (wid == 0) {
        float s = (lid < BLOCK / 32) ? warp_sums[lid] : 0.0f;
        #pragma unroll
        for (int off = 16; off > 0; off >>= 1)
            s += __shfl_xor_sync(0xFFFFFFFFu, s, off);
        if (lid == 0) g_partial[blockIdx.x] = s;
    }
}

__global__ void center_final_kernel(float* __restrict__ out, int nblocks, int n) {
    // single warp folds the partials deterministically
    int lid = threadIdx.x;  // 0..31
    float s = 0.0f;
    for (int i = lid; i < nblocks; i += 32) s += g_partial[i];
    #pragma unroll
    for (int off = 16; off > 0; off >>= 1)
        s += __shfl_xor_sync(0xFFFFFFFFu, s, off);
    if (lid == 0) {
        // 2 - 2*(s/64)/n
        out[0] = 2.0f - (2.0f * (s / 64.0f)) / (float)n;
    }
}

extern "C" void kernel_launch(void* const* d_in, const int* in_sizes, int n_in,
                              void* d_out, int out_size) {
    const float* feature = (const float*)d_in[0];
    const int*   label   = (const int*)d_in[1];
    float*       out     = (float*)d_out;

    int n = in_sizes[1];        // 8192
    int C = in_sizes[0] / n;    // 10000

    int nblocks = (n + BLOCK - 1) / BLOCK;   // 64
    if (nblocks > MAX_BLOCKS) nblocks = MAX_BLOCKS;  // n=8192 -> 64

    center_gather_kernel<<<nblocks, BLOCK>>>(feature, label, n, C);
    center_final_kernel<<<1, 32>>>(out, nblocks, n);
}